// round 10
// baseline (speedup 1.0000x reference)
#include <cuda_runtime.h>
#include <cstdint>

// ---------------- scratch (device globals) ----------------------------------
// windows fp8 e4m3 x8: [s(3)][b(8)][kc(4)][pos(4096)][128B], quad-swizzled
__device__ __align__(256) uint8_t g_win8[(size_t)3 * 8 * 4 * 524288];   // 50 MB
// W1^T fp8 e4m3 x16: [pair(3)][kc(8)][d(512)][128B], quad-swizzled
__device__ __align__(256) uint8_t g_W1f8[(size_t)3 * 8 * 512 * 128];    // 1.5 MB
__device__ float g_lpart[24 * 8 * 4096];   // partial logits [nt*6+dir][b][pos]
__device__ float g_wts[6 * 8 * 4096];      // softmax weights
__device__ float g_faccp[32 * 8 * 512];    // matched partials

// ---------------- helpers ----------------------------------------------------
static __device__ __forceinline__ uint32_t smem_u32(const void* p) {
    return (uint32_t)__cvta_generic_to_shared(p);
}
static __device__ __forceinline__ void cpasync16(uint32_t s, const void* g) {
    asm volatile("cp.async.cg.shared.global [%0], [%1], 16;" :: "r"(s), "l"(g));
}
static __device__ __forceinline__ void cpbulk(uint32_t dst, const void* src,
                                              uint32_t bytes, uint32_t mbar) {
    asm volatile("cp.async.bulk.shared::cluster.global.mbarrier::complete_tx::bytes "
                 "[%0], [%1], %2, [%3];"
                 :: "r"(dst), "l"(src), "r"(bytes), "r"(mbar) : "memory");
}
static __device__ __forceinline__ void ldm4(uint32_t addr, uint32_t& r0, uint32_t& r1,
                                            uint32_t& r2, uint32_t& r3) {
    asm volatile("ldmatrix.sync.aligned.m8n8.x4.shared.b16 {%0,%1,%2,%3}, [%4];"
                 : "=r"(r0), "=r"(r1), "=r"(r2), "=r"(r3) : "r"(addr));
}
static __device__ __forceinline__ void mma_fp8(float* d, const uint32_t* a,
                                               uint32_t b0, uint32_t b1) {
    asm volatile("mma.sync.aligned.m16n8k32.row.col.f32.e4m3.e4m3.f32 "
                 "{%0,%1,%2,%3}, {%4,%5,%6,%7}, {%8,%9}, {%0,%1,%2,%3};"
                 : "+f"(d[0]), "+f"(d[1]), "+f"(d[2]), "+f"(d[3])
                 : "r"(a[0]), "r"(a[1]), "r"(a[2]), "r"(a[3]), "r"(b0), "r"(b1));
}
static __device__ __forceinline__ unsigned short f2e4m3x2(float lo, float hi) {
    unsigned short r;
    asm("cvt.rn.satfinite.e4m3x2.f32 %0, %1, %2;" : "=h"(r) : "f"(hi), "f"(lo));
    return r;
}
#define MBARRIER_INIT(mbar, cnt) \
    asm volatile("mbarrier.init.shared.b64 [%0], %1;" :: "r"((uint32_t)(mbar)), "r"((uint32_t)(cnt)) : "memory")
#define MBARRIER_EXPECT_TX(mbar, tx) \
    asm volatile("mbarrier.arrive.expect_tx.shared.b64 _, [%0], %1;" :: "r"((uint32_t)(mbar)), "r"((uint32_t)(tx)) : "memory")
#define MBARRIER_ARRIVE(mbar) \
    asm volatile("mbarrier.arrive.shared.b64 _, [%0];" :: "r"((uint32_t)(mbar)) : "memory")
#define MBARRIER_WAIT_PARITY(mbar, par) do {                                        \
    uint32_t _m = (uint32_t)(mbar), _p = (uint32_t)(par), _done;                    \
    asm volatile("{\n\t.reg .pred p;\n\t"                                           \
        "mbarrier.try_wait.parity.acquire.cta.shared::cta.b64 p, [%1], %2;\n\t"     \
        "selp.b32 %0, 1, 0, p;\n\t}" : "=r"(_done) : "r"(_m), "r"(_p) : "memory");  \
    if (!_done) {                                                                   \
        asm volatile("{\n\t.reg .pred P1;\n\tWL_%=:\n\t"                            \
            "mbarrier.try_wait.parity.acquire.cta.shared::cta.b64 P1, [%0], %1, 0x989680;\n\t" \
            "@P1 bra.uni WD_%=;\n\tbra.uni WL_%=;\n\tWD_%=:\n\t}"                   \
            :: "r"(_m), "r"(_p) : "memory");                                        \
    }                                                                               \
} while (0)

// ---------------- W1 fp32 -> fp8, transposed + 128B-chunked + swizzled ------
__global__ void convert_w1_kernel(const float* __restrict__ W1) {
    int q = blockIdx.x * 256 + threadIdx.x;   // 786432 byte-pairs
    int c2 = q & 63;               // pair index within 128B row
    int d  = (q >> 6) & 511;
    int kc = (q >> 15) & 7;
    int p  = q >> 18;
    int e  = kc * 128 + c2 * 2;
    float v0 = W1[(size_t)p * 524288 + (size_t)e * 512 + d] * 16.f;
    float v1 = W1[(size_t)p * 524288 + (size_t)(e + 1) * 512 + d] * 16.f;
    int c127 = c2 * 2;
    size_t addr = ((size_t)(p * 8 + kc) * 512 + d) * 128
                + (uint32_t)((((c127 >> 4) ^ (d & 7)) << 4) + (c127 & 15));
    *(unsigned short*)(g_W1f8 + addr) = f2e4m3x2(v0, v1);
}

// ---------------- 3x3x3 avg pool -> fp8 windows, 128B-chunked + swizzled ----
// block = (s, b, cg of 64): 8 channels/block, 80KB smem -> 2 CTAs/SM.
__global__ void __launch_bounds__(256)
pool_kernel(const float* __restrict__ e0, const float* __restrict__ e1,
            const float* __restrict__ e2) {
    extern __shared__ char psm[];
    float* buf0 = (float*)psm;                    // 16 KB
    float* buf1 = (float*)(psm + 16384);          // 16 KB
    float* tmp  = (float*)(psm + 32768);          // 16 KB
    uint8_t* st = (uint8_t*)(psm + 49152);        // 8 ch x 4096 fp8 = 32 KB

    int bx = blockIdx.x;                          // 1536 blocks
    int s = bx >> 9, b = (bx >> 6) & 7, cg = bx & 63;
    const float* e = (s == 0) ? e0 : (s == 1) ? e1 : e2;
    const float* src = e + ((size_t)b << 21) + ((size_t)cg << 15);
    int tid = threadIdx.x;                        // 256
    int wsh = (s == 1) ? 3 : 4;
    int hsh = (s == 2) ? 5 : 4;
    int w = 1 << wsh, h = 1 << hsh, hw = w * h;
    int dd = 4096 >> (wsh + hsh);
    const float SC = 8.0f / 27.0f;

    {   // prefetch channel 0
        uint32_t d0 = smem_u32(buf0);
#pragma unroll
        for (int i = 0; i < 4; i++)
            cpasync16(d0 + (tid + i * 256) * 16, src + (size_t)(tid + i * 256) * 4);
        asm volatile("cp.async.commit_group;");
    }
    for (int cc = 0; cc < 8; cc++) {
        float* cur = (cc & 1) ? buf1 : buf0;
        if (cc < 7) {   // prefetch next channel
            uint32_t dn = smem_u32((cc & 1) ? buf0 : buf1);
            const float* sn = src + (size_t)(cc + 1) * 4096;
#pragma unroll
            for (int i = 0; i < 4; i++)
                cpasync16(dn + (tid + i * 256) * 16, sn + (size_t)(tid + i * 256) * 4);
            asm volatile("cp.async.commit_group;");
            asm volatile("cp.async.wait_group 1;");
        } else {
            asm volatile("cp.async.wait_group 0;");
        }
        __syncthreads();
        for (int p = tid; p < 4096; p += 256) {           // x
            int x = p & (w - 1);
            float v = cur[p];
            if (x > 0) v += cur[p - 1];
            if (x < w - 1) v += cur[p + 1];
            tmp[p] = v;
        }
        __syncthreads();
        for (int p = tid; p < 4096; p += 256) {           // y
            int y = (p >> wsh) & (h - 1);
            float v = tmp[p];
            if (y > 0) v += tmp[p - w];
            if (y < h - 1) v += tmp[p + w];
            cur[p] = v;
        }
        __syncthreads();
        for (int p = tid * 2; p < 4096; p += 512) {       // z + fp8
            int zz = p >> (wsh + hsh);
            float v0 = cur[p], v1 = cur[p + 1];
            if (zz > 0) { v0 += cur[p - hw]; v1 += cur[p + 1 - hw]; }
            if (zz < dd - 1) { v0 += cur[p + hw]; v1 += cur[p + 1 + hw]; }
            *(unsigned short*)(st + cc * 4096 + p) = f2e4m3x2(v0 * SC, v1 * SC);
        }
        __syncthreads();
    }
    // transpose out: 8B (8 channels) per pos into swizzled 128B chunk rows
    int kc = cg >> 4;                 // chunk of 128 channels
    int quad = (cg >> 1) & 7, half = cg & 1;
    uint8_t* chunk = g_win8 + ((size_t)((s * 8 + b) * 4 + kc)) * 524288;
    for (int pos = tid; pos < 4096; pos += 256) {
        uint8_t t8[8];
#pragma unroll
        for (int j = 0; j < 8; j++) t8[j] = st[j * 4096 + pos];
        *(uint2*)(chunk + (size_t)pos * 128
                  + (uint32_t)((quad ^ (pos & 7)) << 4) + half * 8)
            = *(const uint2*)t8;
    }
}

// ---------------- fp8 GEMM (free-running warps, 128B chunks, 2 CTAs/SM) -----
// block (mt, b, z=nt*6+dir): M=128 pos, N=128 hidden, K=1024 in 8 chunks of
// 128B. 256 threads = 8 warps (4m x 2n), warp tile 32x64. 3-stage bulk
// pipeline, full(tx) + empty(8-arrive) mbarriers; no __syncthreads in loop.
#define STG_BYTES 32768            // A 16KB + B 16KB per stage
#define MB_FULL   98304            // 3 full barriers
#define MB_EMPTY  98328            // 3 empty barriers
#define SB1_OFF   98368
#define SW2_OFF   98880
#define SP_OFF    99392
#define GEMM_SMEM 100416

__global__ void __launch_bounds__(256, 2)
gemm_fp8_kernel(const float* __restrict__ b1, const float* __restrict__ W2, int zbase) {
    extern __shared__ char sm[];
    const int tid = threadIdx.x, lane = tid & 31, wid = tid >> 5;
    const uint32_t smb = smem_u32(sm);

    int z = zbase + blockIdx.z, b = blockIdx.y, mt = blockIdx.x;
    int nt = z / 6, dir = z % 6;
    int pair = dir >> 1;
    int pi = (pair == 2) ? 1 : 0;
    int pj = (pair == 0) ? 1 : 2;
    int first  = (dir & 1) ? pj : pi;
    int second = (dir & 1) ? pi : pj;
    const uint8_t* aBase0 = g_win8 + (size_t)(first  * 8 + b) * 4 * 524288 + (size_t)mt * 16384;
    const uint8_t* aBase1 = g_win8 + (size_t)(second * 8 + b) * 4 * 524288 + (size_t)mt * 16384;
    const uint8_t* bBase  = g_W1f8 + (size_t)pair * 524288 + (size_t)nt * 16384;

    float* sB1 = (float*)(sm + SB1_OFF);
    float* sW2 = (float*)(sm + SW2_OFF);
    if (tid < 128) {
        sB1[tid] = b1[pair * 512 + nt * 128 + tid];
        sW2[tid] = W2[pair * 512 + nt * 128 + tid];
    }
    if (tid == 0) {
#pragma unroll
        for (int s = 0; s < 3; s++) {
            MBARRIER_INIT(smb + MB_FULL + s * 8, 1);
            MBARRIER_INIT(smb + MB_EMPTY + s * 8, 8);
        }
    }
    __syncthreads();

    auto issue = [&](int kc, int st) {
        uint32_t mb = smb + MB_FULL + st * 8;
        MBARRIER_EXPECT_TX(mb, 32768u);
        const uint8_t* aSrc = ((kc < 4) ? aBase0 : aBase1) + (size_t)(kc & 3) * 524288;
        cpbulk(smb + st * STG_BYTES, aSrc, 16384u, mb);
        cpbulk(smb + st * STG_BYTES + 16384, bBase + (size_t)kc * 65536, 16384u, mb);
    };
    if (tid == 0) { issue(0, 0); issue(1, 1); issue(2, 2); }

    // base (s=0) smem offsets; k-slice s address = base ^ (s<<5)
    int hi = lane >> 4, lo = lane & 15;
    int wm = wid & 3, wn = wid >> 2;          // 4m x 2n
    uint32_t offA0[2], offB0[4];
#pragma unroll
    for (int m = 0; m < 2; m++) {
        int r = wm * 32 + m * 16 + lo;
        offA0[m] = r * 128 + (uint32_t)((hi ^ (r & 7)) << 4);
    }
#pragma unroll
    for (int g = 0; g < 4; g++) {
        int r = wn * 64 + g * 16 + lo;
        offB0[g] = 16384 + r * 128 + (uint32_t)((hi ^ (r & 7)) << 4);
    }

    float acc[2][8][4] = {};
#pragma unroll
    for (int kc = 0; kc < 8; kc++) {
        const int st = kc % 3;
        const int par = (kc / 3) & 1;
        MBARRIER_WAIT_PARITY(smb + MB_FULL + st * 8, par);
        uint32_t sb = smb + st * STG_BYTES;
#pragma unroll
        for (int s = 0; s < 4; s++) {
            const uint32_t sx = (uint32_t)(s << 5);
            uint32_t a0[4], a1[4];
            ldm4(sb + (offA0[0] ^ sx), a0[0], a0[1], a0[2], a0[3]);
            ldm4(sb + (offA0[1] ^ sx), a1[0], a1[1], a1[2], a1[3]);
#pragma unroll
            for (int g = 0; g < 4; g++) {
                uint32_t bb0, bb1, bb2, bb3;
                ldm4(sb + (offB0[g] ^ sx), bb0, bb1, bb2, bb3);
                mma_fp8(acc[0][g * 2],     a0, bb0, bb2);
                mma_fp8(acc[0][g * 2 + 1], a0, bb1, bb3);
                mma_fp8(acc[1][g * 2],     a1, bb0, bb2);
                mma_fp8(acc[1][g * 2 + 1], a1, bb1, bb3);
            }
        }
        // this warp is done with stage st (mma issue implies ldm reads done)
        if (lane == 0) {
            MBARRIER_ARRIVE(smb + MB_EMPTY + st * 8);
            if (kc < 5 && wid == ((kc + 3) & 7)) {
                MBARRIER_WAIT_PARITY(smb + MB_EMPTY + st * 8, par);
                issue(kc + 3, st);
            }
        }
    }

    // epilogue: relu(acc/128 + b1[n]) * W2[n], reduce over n
    const float INV = 1.0f / 128.0f;
    float part[2][2] = {};
#pragma unroll
    for (int mtl = 0; mtl < 2; mtl++)
#pragma unroll
        for (int f = 0; f < 8; f++) {
            int n = wn * 64 + (f >> 1) * 16 + (f & 1) * 8 + (lane & 3) * 2;
            float b1a = sB1[n], b1b = sB1[n + 1];
            float w2a = sW2[n], w2b = sW2[n + 1];
            part[mtl][0] += fmaxf(acc[mtl][f][0] * INV + b1a, 0.f) * w2a
                          + fmaxf(acc[mtl][f][1] * INV + b1b, 0.f) * w2b;
            part[mtl][1] += fmaxf(acc[mtl][f][2] * INV + b1a, 0.f) * w2a
                          + fmaxf(acc[mtl][f][3] * INV + b1b, 0.f) * w2b;
        }
    float* sp = (float*)(sm + SP_OFF);
#pragma unroll
    for (int mtl = 0; mtl < 2; mtl++)
#pragma unroll
        for (int r = 0; r < 2; r++) {
            float p = part[mtl][r];
            p += __shfl_xor_sync(0xffffffffu, p, 1);
            p += __shfl_xor_sync(0xffffffffu, p, 2);
            if ((lane & 3) == 0)
                sp[wn * 128 + wm * 32 + mtl * 16 + r * 8 + (lane >> 2)] = p;
        }
    __syncthreads();
    if (tid < 128)
        g_lpart[((size_t)z * 8 + b) * 4096 + mt * 128 + tid] = sp[tid] + sp[128 + tid];
}

// ---------------- softmax over N=4096 per (dir,b): sum 4 parts, normalize ---
__global__ void softmax_kernel() {
    int dir = blockIdx.x >> 3, b = blockIdx.x & 7;
    const float* lp0 = g_lpart + ((size_t)(dir)      * 8 + b) * 4096;
    const float* lp1 = g_lpart + ((size_t)(6 + dir)  * 8 + b) * 4096;
    const float* lp2 = g_lpart + ((size_t)(12 + dir) * 8 + b) * 4096;
    const float* lp3 = g_lpart + ((size_t)(18 + dir) * 8 + b) * 4096;
    float* dst = g_wts + ((size_t)dir * 8 + b) * 4096;
    int tid = threadIdx.x;  // 512
    float v[8];
    float mx = -1e30f;
#pragma unroll
    for (int i = 0; i < 8; i++) {
        int p = tid + i * 512;
        v[i] = lp0[p] + lp1[p] + lp2[p] + lp3[p];
        mx = fmaxf(mx, v[i]);
    }
    __shared__ float red[512];
    red[tid] = mx; __syncthreads();
    for (int s = 256; s; s >>= 1) { if (tid < s) red[tid] = fmaxf(red[tid], red[tid + s]); __syncthreads(); }
    mx = red[0]; __syncthreads();
    float sum = 0.f;
#pragma unroll
    for (int i = 0; i < 8; i++) { v[i] = __expf(v[i] - mx); sum += v[i]; }
    red[tid] = sum; __syncthreads();
    for (int s = 256; s; s >>= 1) { if (tid < s) red[tid] += red[tid + s]; __syncthreads(); }
    float inv = 1.f / red[0];
#pragma unroll
    for (int i = 0; i < 8; i++) dst[tid + i * 512] = v[i] * inv;
}

// ---------------- one pass over e: embed sums + all 6 matched terms ---------
__global__ void matched_kernel(const float* __restrict__ e0, const float* __restrict__ e1,
                               const float* __restrict__ e2) {
    int b = blockIdx.y, nc = blockIdx.x;   // 8 x 32
    int n0 = nc * 128;
    __shared__ float w[6][128];
    int tid = threadIdx.x;  // 512
    for (int i = tid; i < 768; i += 512) {
        int d = i >> 7, n = i & 127;
        w[d][n] = g_wts[((size_t)d * 8 + b) * 4096 + n0 + n];
    }
    __syncthreads();
    size_t base = ((size_t)b << 21) + ((size_t)n0 << 9) + tid;
    float acc = 0.f;
    for (int n = 0; n < 128; n++) {
        size_t off = base + ((size_t)n << 9);
        float x0 = e0[off], x1 = e1[off], x2 = e2[off];
        acc += x0 * (1.f + w[1][n] + w[3][n])
             + x1 * (1.f + w[0][n] + w[5][n])
             + x2 * (1.f + w[2][n] + w[4][n]);
    }
    g_faccp[((size_t)nc * 8 + b) * 512 + tid] = acc;
}

// ---------------- fused mean -> LayerNorm -> @Wf + bf -----------------------
__global__ void final_kernel(const float* __restrict__ gamma, const float* __restrict__ beta,
                             const float* __restrict__ Wf, const float* __restrict__ bfv,
                             float* __restrict__ out) {
    int b = blockIdx.x, tid = threadIdx.x;   // 8 x 512
    float f = 0.f;
#pragma unroll 8
    for (int nc = 0; nc < 32; nc++) f += g_faccp[((size_t)nc * 8 + b) * 512 + tid];
    f *= (1.f / 12294.f);
    __shared__ float red[512];
    red[tid] = f; __syncthreads();
    for (int s = 256; s; s >>= 1) { if (tid < s) red[tid] += red[tid + s]; __syncthreads(); }
    float mu = red[0] * (1.f / 512.f); __syncthreads();
    float dv = f - mu;
    red[tid] = dv * dv; __syncthreads();
    for (int s = 256; s; s >>= 1) { if (tid < s) red[tid] += red[tid + s]; __syncthreads(); }
    float var = red[0] * (1.f / 512.f); __syncthreads();
    float ln = dv * rsqrtf(var + 1e-5f) * gamma[tid] + beta[tid];
    __shared__ float sln[512];
    sln[tid] = ln; __syncthreads();
    float o = bfv[tid];
#pragma unroll 4
    for (int k = 0; k < 512; k++) o += sln[k] * Wf[k * 512 + tid];
    out[b * 512 + tid] = o;
}

// ---------------- launch ----------------------------------------------------
extern "C" void kernel_launch(void* const* d_in, const int* in_sizes, int n_in,
                              void* d_out, int out_size) {
    const float* e0    = (const float*)d_in[0];
    const float* e1    = (const float*)d_in[1];
    const float* e2    = (const float*)d_in[2];
    const float* W1    = (const float*)d_in[3];
    const float* b1    = (const float*)d_in[4];
    const float* W2    = (const float*)d_in[5];
    // d_in[6] = b2: constant shift, cancels exactly in softmax -> unused
    const float* gamma = (const float*)d_in[7];
    const float* beta  = (const float*)d_in[8];
    const float* Wf    = (const float*)d_in[9];
    const float* bf    = (const float*)d_in[10];
    float* out = (float*)d_out;

    cudaFuncSetAttribute(pool_kernel, cudaFuncAttributeMaxDynamicSharedMemorySize, 81920);
    cudaFuncSetAttribute(gemm_fp8_kernel, cudaFuncAttributeMaxDynamicSharedMemorySize, GEMM_SMEM);

    convert_w1_kernel<<<3072, 256>>>(W1);                              // 0
    pool_kernel<<<1536, 256, 81920>>>(e0, e1, e2);                     // 1
    gemm_fp8_kernel<<<dim3(32, 8, 6), 256, GEMM_SMEM>>>(b1, W2, 0);    // 2
    gemm_fp8_kernel<<<dim3(32, 8, 6), 256, GEMM_SMEM>>>(b1, W2, 6);    // 3
    gemm_fp8_kernel<<<dim3(32, 8, 6), 256, GEMM_SMEM>>>(b1, W2, 12);   // 4
    gemm_fp8_kernel<<<dim3(32, 8, 6), 256, GEMM_SMEM>>>(b1, W2, 18);   // 5 -> profiled
    softmax_kernel<<<48, 512>>>();
    matched_kernel<<<dim3(32, 8), 512>>>(e0, e1, e2);
    final_kernel<<<8, 512>>>(gamma, beta, Wf, bf, out);
}

// round 12
// speedup vs baseline: 1.1060x; 1.1060x over previous
#include <cuda_runtime.h>
#include <cstdint>

// ---------------- scratch (device globals) ----------------------------------
// windows fp8 e4m3 x8, chunked+swizzled: [s(3)][b(8)][kc(8)][pos(4096)][64B]
__device__ __align__(256) uint8_t g_win8[(size_t)3 * 8 * 8 * 262144];   // 50 MB
// W1^T fp8 e4m3 x16, chunked+swizzled: [pair(3)][kc(16)][d(512)][64B]
__device__ __align__(256) uint8_t g_W1f8[(size_t)3 * 16 * 512 * 64];    // 1.5 MB
__device__ float g_lpart[24 * 8 * 4096];   // partial logits [nt*6+dir][b][pos]
__device__ float g_wts[6 * 8 * 4096];      // softmax weights
__device__ float g_faccp[32 * 8 * 512];    // matched partials

// ---------------- helpers ----------------------------------------------------
static __device__ __forceinline__ uint32_t smem_u32(const void* p) {
    return (uint32_t)__cvta_generic_to_shared(p);
}
static __device__ __forceinline__ void cpasync16(uint32_t s, const void* g) {
    asm volatile("cp.async.cg.shared.global [%0], [%1], 16;" :: "r"(s), "l"(g));
}
static __device__ __forceinline__ void cpbulk(uint32_t dst, const void* src,
                                              uint32_t bytes, uint32_t mbar) {
    asm volatile("cp.async.bulk.shared::cluster.global.mbarrier::complete_tx::bytes "
                 "[%0], [%1], %2, [%3];"
                 :: "r"(dst), "l"(src), "r"(bytes), "r"(mbar) : "memory");
}
static __device__ __forceinline__ void ldm4(uint32_t addr, uint32_t& r0, uint32_t& r1,
                                            uint32_t& r2, uint32_t& r3) {
    asm volatile("ldmatrix.sync.aligned.m8n8.x4.shared.b16 {%0,%1,%2,%3}, [%4];"
                 : "=r"(r0), "=r"(r1), "=r"(r2), "=r"(r3) : "r"(addr));
}
static __device__ __forceinline__ void mma_fp8(float* d, const uint32_t* a,
                                               uint32_t b0, uint32_t b1) {
    asm volatile("mma.sync.aligned.m16n8k32.row.col.f32.e4m3.e4m3.f32 "
                 "{%0,%1,%2,%3}, {%4,%5,%6,%7}, {%8,%9}, {%0,%1,%2,%3};"
                 : "+f"(d[0]), "+f"(d[1]), "+f"(d[2]), "+f"(d[3])
                 : "r"(a[0]), "r"(a[1]), "r"(a[2]), "r"(a[3]), "r"(b0), "r"(b1));
}
static __device__ __forceinline__ unsigned short f2e4m3x2(float lo, float hi) {
    unsigned short r;
    asm("cvt.rn.satfinite.e4m3x2.f32 %0, %1, %2;" : "=h"(r) : "f"(hi), "f"(lo));
    return r;
}
#define MBARRIER_INIT(mbar, cnt) \
    asm volatile("mbarrier.init.shared.b64 [%0], %1;" :: "r"((uint32_t)(mbar)), "r"((uint32_t)(cnt)) : "memory")
#define MBARRIER_EXPECT_TX(mbar, tx) \
    asm volatile("mbarrier.arrive.expect_tx.shared.b64 _, [%0], %1;" :: "r"((uint32_t)(mbar)), "r"((uint32_t)(tx)) : "memory")
#define MBARRIER_ARRIVE(mbar) \
    asm volatile("mbarrier.arrive.shared.b64 _, [%0];" :: "r"((uint32_t)(mbar)) : "memory")
#define MBARRIER_WAIT_PARITY(mbar, par) do {                                        \
    uint32_t _m = (uint32_t)(mbar), _p = (uint32_t)(par), _done;                    \
    asm volatile("{\n\t.reg .pred p;\n\t"                                           \
        "mbarrier.try_wait.parity.acquire.cta.shared::cta.b64 p, [%1], %2;\n\t"     \
        "selp.b32 %0, 1, 0, p;\n\t}" : "=r"(_done) : "r"(_m), "r"(_p) : "memory");  \
    if (!_done) {                                                                   \
        asm volatile("{\n\t.reg .pred P1;\n\tWL_%=:\n\t"                            \
            "mbarrier.try_wait.parity.acquire.cta.shared::cta.b64 P1, [%0], %1, 0x989680;\n\t" \
            "@P1 bra.uni WD_%=;\n\tbra.uni WL_%=;\n\tWD_%=:\n\t}"                   \
            :: "r"(_m), "r"(_p) : "memory");                                        \
    }                                                                               \
} while (0)

// ---------------- W1 fp32 -> fp8, transposed + chunked + swizzled, x16 ------
__global__ void convert_w1_kernel(const float* __restrict__ W1, int off) {
    int q = off + blockIdx.x * 256 + threadIdx.x;   // over 786432 byte pairs
    int c2 = q & 31;              // pair index within 64B row
    int d  = (q >> 5) & 511;
    int kc = (q >> 14) & 15;
    int p  = q >> 18;
    int e  = kc * 64 + c2 * 2;
    float v0 = W1[(size_t)p * 524288 + (size_t)e * 512 + d] * 16.f;
    float v1 = W1[(size_t)p * 524288 + (size_t)(e + 1) * 512 + d] * 16.f;
    int c63 = c2 * 2;
    size_t addr = ((size_t)(p * 16 + kc) * 512 + d) * 64
                + ((((c63 >> 4)) ^ ((d >> 1) & 3)) << 4) + (c63 & 15);
    *(unsigned short*)(g_W1f8 + addr) = f2e4m3x2(v0, v1);
}

// ---------------- 3x3x3 avg pool -> fp8 windows, chunked + swizzled ---------
// block = (s, b, cg of 64): 8 channels/block, 80KB smem -> 2 CTAs/SM.
__global__ void __launch_bounds__(256)
pool_kernel(const float* __restrict__ e0, const float* __restrict__ e1,
            const float* __restrict__ e2) {
    extern __shared__ char psm[];
    float* buf0 = (float*)psm;                    // 16 KB
    float* buf1 = (float*)(psm + 16384);          // 16 KB
    float* tmp  = (float*)(psm + 32768);          // 16 KB
    uint8_t* st = (uint8_t*)(psm + 49152);        // 8 ch x 4096 fp8 = 32 KB

    int bx = blockIdx.x;                          // 1536 blocks
    int s = bx >> 9, b = (bx >> 6) & 7, cg = bx & 63;
    const float* e = (s == 0) ? e0 : (s == 1) ? e1 : e2;
    const float* src = e + ((size_t)b << 21) + ((size_t)cg << 15);
    int tid = threadIdx.x;                        // 256
    int wsh = (s == 1) ? 3 : 4;
    int hsh = (s == 2) ? 5 : 4;
    int w = 1 << wsh, h = 1 << hsh, hw = w * h;
    int dd = 4096 >> (wsh + hsh);
    const float SC = 8.0f / 27.0f;

    {   // prefetch channel 0
        uint32_t d0 = smem_u32(buf0);
#pragma unroll
        for (int i = 0; i < 4; i++)
            cpasync16(d0 + (tid + i * 256) * 16, src + (size_t)(tid + i * 256) * 4);
        asm volatile("cp.async.commit_group;");
    }
    for (int cc = 0; cc < 8; cc++) {
        float* cur = (cc & 1) ? buf1 : buf0;
        if (cc < 7) {   // prefetch next channel
            uint32_t dn = smem_u32((cc & 1) ? buf0 : buf1);
            const float* sn = src + (size_t)(cc + 1) * 4096;
#pragma unroll
            for (int i = 0; i < 4; i++)
                cpasync16(dn + (tid + i * 256) * 16, sn + (size_t)(tid + i * 256) * 4);
            asm volatile("cp.async.commit_group;");
            asm volatile("cp.async.wait_group 1;");
        } else {
            asm volatile("cp.async.wait_group 0;");
        }
        __syncthreads();
        for (int p = tid; p < 4096; p += 256) {           // x
            int x = p & (w - 1);
            float v = cur[p];
            if (x > 0) v += cur[p - 1];
            if (x < w - 1) v += cur[p + 1];
            tmp[p] = v;
        }
        __syncthreads();
        for (int p = tid; p < 4096; p += 256) {           // y
            int y = (p >> wsh) & (h - 1);
            float v = tmp[p];
            if (y > 0) v += tmp[p - w];
            if (y < h - 1) v += tmp[p + w];
            cur[p] = v;
        }
        __syncthreads();
        for (int p = tid * 2; p < 4096; p += 512) {       // z + fp8
            int zz = p >> (wsh + hsh);
            float v0 = cur[p], v1 = cur[p + 1];
            if (zz > 0) { v0 += cur[p - hw]; v1 += cur[p + 1 - hw]; }
            if (zz < dd - 1) { v0 += cur[p + hw]; v1 += cur[p + 1 + hw]; }
            *(unsigned short*)(st + cc * 4096 + p) = f2e4m3x2(v0 * SC, v1 * SC);
        }
        __syncthreads();
    }
    // transpose out: 8B (8 channels) per pos into swizzled chunk rows
    uint8_t* chunk = g_win8 + ((size_t)((s * 8 + b) * 8 + (cg >> 3))) * 262144;
    int q0 = (cg >> 1) & 3, half = cg & 1;
    for (int pos = tid; pos < 4096; pos += 256) {
        uint8_t t8[8];
#pragma unroll
        for (int j = 0; j < 8; j++) t8[j] = st[j * 4096 + pos];
        *(uint2*)(chunk + (size_t)pos * 64
                  + (uint32_t)((q0 ^ ((pos >> 1) & 3)) << 4) + half * 8)
            = *(const uint2*)t8;
    }
}

// ---------------- fp8 GEMM (free-running warps, 6-stage pipeline) -----------
// block (mt, b, z=nt*6+dir): M=128 pos, N=128 hidden, K=1024 in 16 chunks of
// 64B. 256 threads = 8 warps (4m x 2n), warp tile 32x64. 6-stage bulk pipeline
// with full(tx) + empty(8-arrive) mbarriers; NO __syncthreads in mainloop.
// SMEM map: 6*16384=98304 stages | full mbars 98304..98352 | empty 98352..98400
//           sB1 98400..98912 | sW2 98912..99424 | sp 99424..100448
#define STG_BYTES 16384            // A 8KB + B 8KB per stage
#define MB_FULL   98304            // 6 full barriers
#define MB_EMPTY  98352            // 6 empty barriers
#define SB1_OFF   98400
#define SW2_OFF   98912
#define SP_OFF    99424
#define GEMM_SMEM 100448           // fixed: sp needs 256 floats = 1024 B

__global__ void __launch_bounds__(256, 2)
gemm_fp8_kernel(const float* __restrict__ b1, const float* __restrict__ W2) {
    extern __shared__ char sm[];
    const int tid = threadIdx.x, lane = tid & 31, wid = tid >> 5;
    const uint32_t smb = smem_u32(sm);

    int z = blockIdx.z, b = blockIdx.y, mt = blockIdx.x;
    int nt = z / 6, dir = z % 6;
    int pair = dir >> 1;
    int pi = (pair == 2) ? 1 : 0;
    int pj = (pair == 0) ? 1 : 2;
    int first  = (dir & 1) ? pj : pi;
    int second = (dir & 1) ? pi : pj;
    const uint8_t* aBase0 = g_win8 + (size_t)(first  * 8 + b) * 8 * 262144 + (size_t)mt * 8192;
    const uint8_t* aBase1 = g_win8 + (size_t)(second * 8 + b) * 8 * 262144 + (size_t)mt * 8192;
    const uint8_t* bBase  = g_W1f8 + (size_t)pair * 524288 + (size_t)nt * 8192;

    float* sB1 = (float*)(sm + SB1_OFF);
    float* sW2 = (float*)(sm + SW2_OFF);
    if (tid < 128) {
        sB1[tid] = b1[pair * 512 + nt * 128 + tid];
        sW2[tid] = W2[pair * 512 + nt * 128 + tid];
    }
    if (tid == 0) {
#pragma unroll
        for (int s = 0; s < 6; s++) {
            MBARRIER_INIT(smb + MB_FULL + s * 8, 1);
            MBARRIER_INIT(smb + MB_EMPTY + s * 8, 8);
        }
    }
    __syncthreads();

    auto issue = [&](int kc, int st) {
        uint32_t mb = smb + MB_FULL + st * 8;
        MBARRIER_EXPECT_TX(mb, 16384u);
        const uint8_t* aSrc = ((kc < 8) ? aBase0 : aBase1) + (size_t)(kc & 7) * 262144;
        cpbulk(smb + st * STG_BYTES, aSrc, 8192u, mb);
        cpbulk(smb + st * STG_BYTES + 8192, bBase + (size_t)kc * 32768, 8192u, mb);
    };
    if (tid == 0) {
        issue(0, 0); issue(1, 1); issue(2, 2);
        issue(3, 3); issue(4, 4); issue(5, 5);
    }

    // per-thread smem offsets within a stage (swizzle baked in)
    int hi = lane >> 4, lo = lane & 15;
    int wm = wid & 3, wn = wid >> 2;          // 4m x 2n
    uint32_t offA[2][2], offB[2][4];
#pragma unroll
    for (int s = 0; s < 2; s++) {
#pragma unroll
        for (int m = 0; m < 2; m++) {
            int r = wm * 32 + m * 16 + lo;
            offA[s][m] = r * 64 + (uint32_t)(((s * 2 + hi) ^ ((r >> 1) & 3)) << 4);
        }
#pragma unroll
        for (int g = 0; g < 4; g++) {
            int r = wn * 64 + g * 16 + lo;
            offB[s][g] = 8192 + r * 64 + (uint32_t)(((s * 2 + hi) ^ ((r >> 1) & 3)) << 4);
        }
    }

    float acc[2][8][4] = {};
#pragma unroll
    for (int kc = 0; kc < 16; kc++) {
        const int st = kc % 6;
        const int par = (kc / 6) & 1;
        MBARRIER_WAIT_PARITY(smb + MB_FULL + st * 8, par);
        uint32_t sb = smb + st * STG_BYTES;
#pragma unroll
        for (int s = 0; s < 2; s++) {
            uint32_t a0[4], a1[4];
            ldm4(sb + offA[s][0], a0[0], a0[1], a0[2], a0[3]);
            ldm4(sb + offA[s][1], a1[0], a1[1], a1[2], a1[3]);
#pragma unroll
            for (int g = 0; g < 4; g++) {
                uint32_t bb0, bb1, bb2, bb3;
                ldm4(sb + offB[s][g], bb0, bb1, bb2, bb3);
                mma_fp8(acc[0][g * 2],     a0, bb0, bb2);
                mma_fp8(acc[0][g * 2 + 1], a0, bb1, bb3);
                mma_fp8(acc[1][g * 2],     a1, bb0, bb2);
                mma_fp8(acc[1][g * 2 + 1], a1, bb1, bb3);
            }
        }
        // signal this warp done with stage st (mma issue implies ldm reads done)
        if (lane == 0) {
            MBARRIER_ARRIVE(smb + MB_EMPTY + st * 8);
            if (kc < 10 && wid == ((kc + 6) & 7)) {
                // reuse of stage st: wait for the prior consumption to drain
                MBARRIER_WAIT_PARITY(smb + MB_EMPTY + st * 8, (((kc + 6) / 6) - 1) & 1);
                issue(kc + 6, st);
            }
        }
    }

    // epilogue: relu(acc/128 + b1[n]) * W2[n], reduce over n
    const float INV = 1.0f / 128.0f;
    float part[2][2] = {};
#pragma unroll
    for (int mtl = 0; mtl < 2; mtl++)
#pragma unroll
        for (int f = 0; f < 8; f++) {
            int n = wn * 64 + (f >> 1) * 16 + (f & 1) * 8 + (lane & 3) * 2;
            float b1a = sB1[n], b1b = sB1[n + 1];
            float w2a = sW2[n], w2b = sW2[n + 1];
            part[mtl][0] += fmaxf(acc[mtl][f][0] * INV + b1a, 0.f) * w2a
                          + fmaxf(acc[mtl][f][1] * INV + b1b, 0.f) * w2b;
            part[mtl][1] += fmaxf(acc[mtl][f][2] * INV + b1a, 0.f) * w2a
                          + fmaxf(acc[mtl][f][3] * INV + b1b, 0.f) * w2b;
        }
    float* sp = (float*)(sm + SP_OFF);
#pragma unroll
    for (int mtl = 0; mtl < 2; mtl++)
#pragma unroll
        for (int r = 0; r < 2; r++) {
            float p = part[mtl][r];
            p += __shfl_xor_sync(0xffffffffu, p, 1);
            p += __shfl_xor_sync(0xffffffffu, p, 2);
            if ((lane & 3) == 0)
                sp[wn * 128 + wm * 32 + mtl * 16 + r * 8 + (lane >> 2)] = p;
        }
    __syncthreads();
    if (tid < 128)
        g_lpart[((size_t)z * 8 + b) * 4096 + mt * 128 + tid] = sp[tid] + sp[128 + tid];
}

// ---------------- softmax over N=4096 per (dir,b): sum 4 parts, normalize ---
__global__ void softmax_kernel() {
    int dir = blockIdx.x >> 3, b = blockIdx.x & 7;
    const float* lp0 = g_lpart + ((size_t)(dir)      * 8 + b) * 4096;
    const float* lp1 = g_lpart + ((size_t)(6 + dir)  * 8 + b) * 4096;
    const float* lp2 = g_lpart + ((size_t)(12 + dir) * 8 + b) * 4096;
    const float* lp3 = g_lpart + ((size_t)(18 + dir) * 8 + b) * 4096;
    float* dst = g_wts + ((size_t)dir * 8 + b) * 4096;
    int tid = threadIdx.x;  // 512
    float v[8];
    float mx = -1e30f;
#pragma unroll
    for (int i = 0; i < 8; i++) {
        int p = tid + i * 512;
        v[i] = lp0[p] + lp1[p] + lp2[p] + lp3[p];
        mx = fmaxf(mx, v[i]);
    }
    __shared__ float red[512];
    red[tid] = mx; __syncthreads();
    for (int s = 256; s; s >>= 1) { if (tid < s) red[tid] = fmaxf(red[tid], red[tid + s]); __syncthreads(); }
    mx = red[0]; __syncthreads();
    float sum = 0.f;
#pragma unroll
    for (int i = 0; i < 8; i++) { v[i] = __expf(v[i] - mx); sum += v[i]; }
    red[tid] = sum; __syncthreads();
    for (int s = 256; s; s >>= 1) { if (tid < s) red[tid] += red[tid + s]; __syncthreads(); }
    float inv = 1.f / red[0];
#pragma unroll
    for (int i = 0; i < 8; i++) dst[tid + i * 512] = v[i] * inv;
}

// ---------------- one pass over e: embed sums + all 6 matched terms ---------
__global__ void matched_kernel(const float* __restrict__ e0, const float* __restrict__ e1,
                               const float* __restrict__ e2) {
    int b = blockIdx.y, nc = blockIdx.x;   // 8 x 32
    int n0 = nc * 128;
    __shared__ float w[6][128];
    int tid = threadIdx.x;  // 512
    for (int i = tid; i < 768; i += 512) {
        int d = i >> 7, n = i & 127;
        w[d][n] = g_wts[((size_t)d * 8 + b) * 4096 + n0 + n];
    }
    __syncthreads();
    size_t base = ((size_t)b << 21) + ((size_t)n0 << 9) + tid;
    float acc = 0.f;
    for (int n = 0; n < 128; n++) {
        size_t off = base + ((size_t)n << 9);
        float x0 = e0[off], x1 = e1[off], x2 = e2[off];
        acc += x0 * (1.f + w[1][n] + w[3][n])
             + x1 * (1.f + w[0][n] + w[5][n])
             + x2 * (1.f + w[2][n] + w[4][n]);
    }
    g_faccp[((size_t)nc * 8 + b) * 512 + tid] = acc;
}

// ---------------- fused mean -> LayerNorm -> @Wf + bf -----------------------
__global__ void final_kernel(const float* __restrict__ gamma, const float* __restrict__ beta,
                             const float* __restrict__ Wf, const float* __restrict__ bfv,
                             float* __restrict__ out) {
    int b = blockIdx.x, tid = threadIdx.x;   // 8 x 512
    float f = 0.f;
#pragma unroll 8
    for (int nc = 0; nc < 32; nc++) f += g_faccp[((size_t)nc * 8 + b) * 512 + tid];
    f *= (1.f / 12294.f);
    __shared__ float red[512];
    red[tid] = f; __syncthreads();
    for (int s = 256; s; s >>= 1) { if (tid < s) red[tid] += red[tid + s]; __syncthreads(); }
    float mu = red[0] * (1.f / 512.f); __syncthreads();
    float dv = f - mu;
    red[tid] = dv * dv; __syncthreads();
    for (int s = 256; s; s >>= 1) { if (tid < s) red[tid] += red[tid + s]; __syncthreads(); }
    float var = red[0] * (1.f / 512.f); __syncthreads();
    float ln = dv * rsqrtf(var + 1e-5f) * gamma[tid] + beta[tid];
    __shared__ float sln[512];
    sln[tid] = ln; __syncthreads();
    float o = bfv[tid];
#pragma unroll 4
    for (int k = 0; k < 512; k++) o += sln[k] * Wf[k * 512 + tid];
    out[b * 512 + tid] = o;
}

// ---------------- launch ----------------------------------------------------
extern "C" void kernel_launch(void* const* d_in, const int* in_sizes, int n_in,
                              void* d_out, int out_size) {
    const float* e0    = (const float*)d_in[0];
    const float* e1    = (const float*)d_in[1];
    const float* e2    = (const float*)d_in[2];
    const float* W1    = (const float*)d_in[3];
    const float* b1    = (const float*)d_in[4];
    const float* W2    = (const float*)d_in[5];
    // d_in[6] = b2: constant shift, cancels exactly in softmax -> unused
    const float* gamma = (const float*)d_in[7];
    const float* beta  = (const float*)d_in[8];
    const float* Wf    = (const float*)d_in[9];
    const float* bf    = (const float*)d_in[10];
    float* out = (float*)d_out;

    cudaFuncSetAttribute(pool_kernel, cudaFuncAttributeMaxDynamicSharedMemorySize, 81920);
    cudaFuncSetAttribute(gemm_fp8_kernel, cudaFuncAttributeMaxDynamicSharedMemorySize, GEMM_SMEM);

    convert_w1_kernel<<<768, 256>>>(W1, 0);          // 0
    convert_w1_kernel<<<768, 256>>>(W1, 196608);     // 1
    convert_w1_kernel<<<768, 256>>>(W1, 393216);     // 2
    convert_w1_kernel<<<768, 256>>>(W1, 589824);     // 3
    pool_kernel<<<1536, 256, 81920>>>(e0, e1, e2);   // 4
    gemm_fp8_kernel<<<dim3(32, 8, 24), 256, GEMM_SMEM>>>(b1, W2);  // 5 -> profiled
    softmax_kernel<<<48, 512>>>();
    matched_kernel<<<dim3(32, 8), 512>>>(e0, e1, e2);
    final_kernel<<<8, 512>>>(gamma, beta, Wf, bf, out);
}